// round 1
// baseline (speedup 1.0000x reference)
#include <cuda_runtime.h>
#include <cstdint>
#include <cstddef>

#define DEVINL __device__ __forceinline__

// ======================= f32x2 packed helpers (Blackwell FFMA2) =======================
DEVINL unsigned long long pack2(float lo, float hi) {
    unsigned long long d;
    asm("mov.b64 %0, {%1, %2};" : "=l"(d)
        : "r"(__float_as_uint(lo)), "r"(__float_as_uint(hi)));
    return d;
}
DEVINL void unpack2(unsigned long long v, float& lo, float& hi) {
    unsigned int a, b;
    asm("mov.b64 {%0, %1}, %2;" : "=r"(a), "=r"(b) : "l"(v));
    lo = __uint_as_float(a);
    hi = __uint_as_float(b);
}
DEVINL unsigned long long fma2(unsigned long long a, unsigned long long b, unsigned long long c) {
    unsigned long long d;
    asm("fma.rn.f32x2 %0, %1, %2, %3;" : "=l"(d) : "l"(a), "l"(b), "l"(c));
    return d;
}
DEVINL unsigned long long mul2(unsigned long long a, unsigned long long b) {
    unsigned long long d;
    asm("mul.rn.f32x2 %0, %1, %2;" : "=l"(d) : "l"(a), "l"(b));
    return d;
}

// ======================= problem constants =======================
constexpr int B_   = 4;
constexpr int C_   = 256;
constexpr int N_   = 4096;   // H*W
constexpr int DQK  = 32;
constexpr int DV   = 256;

// ======================= scratch (no allocs allowed) =======================
__device__ float g_Q[(size_t)B_ * N_ * DQK];   // [B][N][32]
__device__ float g_K[(size_t)B_ * N_ * DQK];   // [B][N][32]
__device__ float g_V[(size_t)B_ * N_ * DV];    // [B][N][256]

// ======================= projection kernel =======================
// Computes Q,K,V = W * x (+bias) as one stacked GEMM: 320 outputs per pixel.
// CTA: (batch, 64-pixel tile). 256 threads: thread = (pixel p = t&63, out-group g = t>>6),
// each thread owns 80 outputs (40 f32x2 accumulators).
constexpr int PT     = 64;    // pixels per CTA
constexpr int MTOT   = 320;   // 32 q + 32 k + 256 v
constexpr int CCH    = 64;    // channel chunk
constexpr int WSTR   = 324;   // padded smem row stride (floats), 16B-aligned rows
constexpr int PROJ_SMEM = (CCH * PT + CCH * WSTR) * 4;   // 99328 bytes

__global__ void __launch_bounds__(256, 2) proj_kernel(
    const float* __restrict__ x,
    const float* __restrict__ Wq, const float* __restrict__ bq,
    const float* __restrict__ Wk, const float* __restrict__ bk,
    const float* __restrict__ Wv, const float* __restrict__ bv)
{
    extern __shared__ __align__(16) char dynsm[];
    float* xs = (float*)dynsm;             // [CCH][PT]
    float* Ws = (float*)dynsm + CCH * PT;  // [CCH][WSTR], Ws[cc][m] = W[m][c0+cc]

    const int t  = threadIdx.x;
    const int b  = blockIdx.y;
    const int n0 = blockIdx.x * PT;
    const int p  = t & 63;
    const int g  = t >> 6;   // 0..3, 80 outputs each

    unsigned long long A[40];
#pragma unroll
    for (int k = 0; k < 40; k++) A[k] = 0ull;

    for (int c0 = 0; c0 < C_; c0 += CCH) {
        __syncthreads();
        // stage x chunk [CCH][PT]
#pragma unroll
        for (int k = 0; k < (CCH * PT) / 256; k++) {
            int idx = t + k * 256;
            int cc = idx >> 6, pp = idx & 63;
            xs[idx] = x[((size_t)b * C_ + (c0 + cc)) * N_ + (n0 + pp)];
        }
        // stage W transposed: Ws[cc][m]
        for (int idx = t; idx < MTOT * CCH; idx += 256) {
            int m = idx / CCH, cc = idx % CCH;
            int c = c0 + cc;
            float w;
            if (m < 32)       w = Wq[m * C_ + c];
            else if (m < 64)  w = Wk[(m - 32) * C_ + c];
            else              w = Wv[(m - 64) * C_ + c];
            Ws[cc * WSTR + m] = w;
        }
        __syncthreads();

#pragma unroll 4
        for (int cc = 0; cc < CCH; cc++) {
            float xv = xs[cc * 64 + p];
            unsigned long long xx = pack2(xv, xv);
            const ulonglong2* wr = (const ulonglong2*)(Ws + cc * WSTR + g * 80);
#pragma unroll
            for (int k = 0; k < 20; k++) {
                ulonglong2 w4 = wr[k];       // 4 consecutive W values (broadcast in warp)
                A[2 * k]     = fma2(xx, w4.x, A[2 * k]);
                A[2 * k + 1] = fma2(xx, w4.y, A[2 * k + 1]);
            }
        }
    }

    // write out with bias
    const int n = n0 + p;
#pragma unroll
    for (int k = 0; k < 40; k++) {
        float v0, v1;
        unpack2(A[k], v0, v1);
        int o = g * 80 + 2 * k;
        float vals[2] = {v0, v1};
#pragma unroll
        for (int u = 0; u < 2; u++) {
            int oo = o + u;
            float val = vals[u];
            if (oo < 32)
                g_Q[((size_t)b * N_ + n) * DQK + oo] = val + bq[oo];
            else if (oo < 64)
                g_K[((size_t)b * N_ + n) * DQK + (oo - 32)] = val + bk[oo - 32];
            else
                g_V[((size_t)b * N_ + n) * DV + (oo - 64)] = val + bv[oo - 64];
        }
    }
}

// ======================= flash attention kernel =======================
// CTA: (batch, 64-query-row tile). 256 threads: thread = (row r = t>>2, colgroup cg = t&3).
// Each thread accumulates O[r][cg*64 .. cg*64+63] as 32 f32x2 regs.
// K/V tiles (BN=64 keys) double-buffered in smem via cp.async, 128B XOR swizzle.
constexpr int BM = 64, BN = 64;
constexpr uint32_t AV0 = 0;
constexpr uint32_t AV1 = 65536;
constexpr uint32_t AK0 = 131072;
constexpr uint32_t AK1 = 131072 + 8192;
constexpr int ATTN_SMEM = 147456;

DEVINL uint32_t swz(uint32_t off) { return off ^ ((off >> 3) & 0x70u); }

DEVINL void cp16(uint32_t dst, const void* src) {
    asm volatile("cp.async.cg.shared.global [%0], [%1], 16;" :: "r"(dst), "l"(src));
}

__global__ void __launch_bounds__(256, 1) attn_kernel(float* __restrict__ out)
{
    extern __shared__ __align__(16) char dynsm[];
    const uint32_t sb = (uint32_t)__cvta_generic_to_shared(dynsm);
    const int t  = threadIdx.x;
    const int b  = blockIdx.y;
    const int n0 = blockIdx.x * BM;
    const int r  = t >> 2;
    const int cg = t & 3;

    // q row (32 floats) packed into 16 f32x2 regs (replicated across the 4 cg lanes)
    unsigned long long q2[16];
    {
        const float4* qr = (const float4*)(g_Q + ((size_t)b * N_ + n0 + r) * DQK);
#pragma unroll
        for (int i = 0; i < 8; i++) {
            float4 f = qr[i];
            q2[2 * i]     = pack2(f.x, f.y);
            q2[2 * i + 1] = pack2(f.z, f.w);
        }
    }

    unsigned long long O2[32];
#pragma unroll
    for (int i = 0; i < 32; i++) O2[i] = 0ull;
    float m = -1e30f, l = 0.f;

    const char* kbase = (const char*)(g_K + (size_t)b * N_ * DQK);
    const char* vbase = (const char*)(g_V + (size_t)b * N_ * DV);

    // prologue: tile 0 -> buffer 0
#pragma unroll
    for (int k = 0; k < 2; k++) {
        uint32_t off = (uint32_t)(t + k * 256) * 16;
        cp16(sb + AK0 + swz(off), kbase + off);
    }
#pragma unroll
    for (int k = 0; k < 16; k++) {
        uint32_t off = (uint32_t)(t + k * 256) * 16;
        cp16(sb + AV0 + swz(off), vbase + off);
    }
    asm volatile("cp.async.commit_group;");

    const int NBLK = N_ / BN;   // 64
    for (int blk = 0; blk < NBLK; blk++) {
        const int bi = blk & 1;
        if (blk + 1 < NBLK) {
            const int nb = (blk + 1) & 1;
            const char* kt = kbase + (size_t)(blk + 1) * BN * DQK * 4;
            const char* vt = vbase + (size_t)(blk + 1) * BN * DV * 4;
            const uint32_t kdst = sb + (nb ? AK1 : AK0);
            const uint32_t vdst = sb + (nb ? AV1 : AV0);
#pragma unroll
            for (int k = 0; k < 2; k++) {
                uint32_t off = (uint32_t)(t + k * 256) * 16;
                cp16(kdst + swz(off), kt + off);
            }
#pragma unroll
            for (int k = 0; k < 16; k++) {
                uint32_t off = (uint32_t)(t + k * 256) * 16;
                cp16(vdst + swz(off), vt + off);
            }
            asm volatile("cp.async.commit_group;");
            asm volatile("cp.async.wait_group 1;");
        } else {
            asm volatile("cp.async.wait_group 0;");
        }
        __syncthreads();

        const char* ks = dynsm + (bi ? AK1 : AK0);
        const char* vs = dynsm + (bi ? AV1 : AV0);

        // ---- S = q . k, 16 keys per thread (j = jj*4 + cg) ----
        float p_[16];
        float bmax = -1e30f;
#pragma unroll
        for (int jj = 0; jj < 16; jj++) {
            int j = jj * 4 + cg;
            unsigned long long s0 = 0ull, s1 = 0ull;
#pragma unroll
            for (int i = 0; i < 8; i++) {
                uint32_t off = (uint32_t)(j * 128 + i * 16);
                ulonglong2 kk = *(const ulonglong2*)(ks + swz(off));
                s0 = fma2(q2[2 * i], kk.x, s0);
                s1 = fma2(q2[2 * i + 1], kk.y, s1);
            }
            float a0, a1, c0, c1;
            unpack2(s0, a0, a1);
            unpack2(s1, c0, c1);
            float s = (a0 + a1) + (c0 + c1);
            p_[jj] = s;
            bmax = fmaxf(bmax, s);
        }
        bmax = fmaxf(bmax, __shfl_xor_sync(0xffffffffu, bmax, 1, 4));
        bmax = fmaxf(bmax, __shfl_xor_sync(0xffffffffu, bmax, 2, 4));

        // ---- online softmax ----
        const float L2E = 1.4426950408889634f;
        float mn   = fmaxf(m, bmax);
        float corr = exp2f((m - mn) * L2E);
        float ls = 0.f;
#pragma unroll
        for (int jj = 0; jj < 16; jj++) {
            float pv = exp2f((p_[jj] - mn) * L2E);
            p_[jj] = pv;
            ls += pv;
        }
        ls += __shfl_xor_sync(0xffffffffu, ls, 1, 4);
        ls += __shfl_xor_sync(0xffffffffu, ls, 2, 4);
        l = l * corr + ls;
        m = mn;
        unsigned long long cc2 = pack2(corr, corr);
#pragma unroll
        for (int i = 0; i < 32; i++) O2[i] = mul2(O2[i], cc2);

        // ---- O += P @ V ----
#pragma unroll 4
        for (int j = 0; j < BN; j++) {
            float pj = __shfl_sync(0xffffffffu, p_[j >> 2], j & 3, 4);
            unsigned long long pp = pack2(pj, pj);
            uint32_t rowoff = (uint32_t)(j * 1024 + cg * 256);
#pragma unroll
            for (int i = 0; i < 16; i++) {
                ulonglong2 vv = *(const ulonglong2*)(vs + swz(rowoff + i * 16));
                O2[2 * i]     = fma2(pp, vv.x, O2[2 * i]);
                O2[2 * i + 1] = fma2(pp, vv.y, O2[2 * i + 1]);
            }
        }
        __syncthreads();
    }

    // ---- epilogue: out[b][c][n] = O[r][c] / l ----
    const float inv = 1.f / l;
    const int n = n0 + r;
    float* ob = out + (size_t)b * C_ * N_;
#pragma unroll
    for (int i = 0; i < 32; i++) {
        float v0, v1;
        unpack2(O2[i], v0, v1);
        int c = cg * 64 + 2 * i;
        ob[(size_t)c * N_ + n]       = v0 * inv;
        ob[(size_t)(c + 1) * N_ + n] = v1 * inv;
    }
}

// ======================= launch =======================
extern "C" void kernel_launch(void* const* d_in, const int* in_sizes, int n_in,
                              void* d_out, int out_size)
{
    const float* x  = (const float*)d_in[0];
    const float* Wq = (const float*)d_in[1];
    const float* bq = (const float*)d_in[2];
    const float* Wk = (const float*)d_in[3];
    const float* bk = (const float*)d_in[4];
    const float* Wv = (const float*)d_in[5];
    const float* bv = (const float*)d_in[6];
    float* out = (float*)d_out;

    cudaFuncSetAttribute(proj_kernel, cudaFuncAttributeMaxDynamicSharedMemorySize, PROJ_SMEM);
    cudaFuncSetAttribute(attn_kernel, cudaFuncAttributeMaxDynamicSharedMemorySize, ATTN_SMEM);

    proj_kernel<<<dim3(N_ / PT, B_), 256, PROJ_SMEM>>>(x, Wq, bq, Wk, bk, Wv, bv);
    attn_kernel<<<dim3(N_ / BM, B_), 256, ATTN_SMEM>>>(out);
}

// round 2
// speedup vs baseline: 2.2636x; 2.2636x over previous
#include <cuda_runtime.h>
#include <cstdint>
#include <cstddef>

#define DEVINL __device__ __forceinline__

// ======================= f32x2 packed helpers (Blackwell FFMA2) =======================
DEVINL unsigned long long pack2(float lo, float hi) {
    unsigned long long d;
    asm("mov.b64 %0, {%1, %2};" : "=l"(d)
        : "r"(__float_as_uint(lo)), "r"(__float_as_uint(hi)));
    return d;
}
DEVINL void unpack2(unsigned long long v, float& lo, float& hi) {
    unsigned int a, b;
    asm("mov.b64 {%0, %1}, %2;" : "=r"(a), "=r"(b) : "l"(v));
    lo = __uint_as_float(a);
    hi = __uint_as_float(b);
}
DEVINL unsigned long long fma2(unsigned long long a, unsigned long long b, unsigned long long c) {
    unsigned long long d;
    asm("fma.rn.f32x2 %0, %1, %2, %3;" : "=l"(d) : "l"(a), "l"(b), "l"(c));
    return d;
}
DEVINL unsigned long long mul2(unsigned long long a, unsigned long long b) {
    unsigned long long d;
    asm("mul.rn.f32x2 %0, %1, %2;" : "=l"(d) : "l"(a), "l"(b));
    return d;
}

// ======================= problem constants =======================
constexpr int B_   = 4;
constexpr int C_   = 256;
constexpr int N_   = 4096;   // H*W
constexpr int DQK  = 32;
constexpr int DV   = 256;

// ======================= scratch (no allocs allowed) =======================
__device__ float g_Q[(size_t)B_ * N_ * DQK];   // [B][N][32]
__device__ float g_K[(size_t)B_ * N_ * DQK];   // [B][N][32]
__device__ float g_V[(size_t)B_ * N_ * DV];    // [B][N][256]

// ======================= projection kernel (unchanged) =======================
constexpr int PT     = 64;
constexpr int MTOT   = 320;
constexpr int CCH    = 64;
constexpr int WSTR   = 324;
constexpr int PROJ_SMEM = (CCH * PT + CCH * WSTR) * 4;

__global__ void __launch_bounds__(256, 2) proj_kernel(
    const float* __restrict__ x,
    const float* __restrict__ Wq, const float* __restrict__ bq,
    const float* __restrict__ Wk, const float* __restrict__ bk,
    const float* __restrict__ Wv, const float* __restrict__ bv)
{
    extern __shared__ __align__(16) char dynsm[];
    float* xs = (float*)dynsm;
    float* Ws = (float*)dynsm + CCH * PT;

    const int t  = threadIdx.x;
    const int b  = blockIdx.y;
    const int n0 = blockIdx.x * PT;
    const int p  = t & 63;
    const int g  = t >> 6;

    unsigned long long A[40];
#pragma unroll
    for (int k = 0; k < 40; k++) A[k] = 0ull;

    for (int c0 = 0; c0 < C_; c0 += CCH) {
        __syncthreads();
#pragma unroll
        for (int k = 0; k < (CCH * PT) / 256; k++) {
            int idx = t + k * 256;
            int cc = idx >> 6, pp = idx & 63;
            xs[idx] = x[((size_t)b * C_ + (c0 + cc)) * N_ + (n0 + pp)];
        }
        for (int idx = t; idx < MTOT * CCH; idx += 256) {
            int m = idx / CCH, cc = idx % CCH;
            int c = c0 + cc;
            float w;
            if (m < 32)       w = Wq[m * C_ + c];
            else if (m < 64)  w = Wk[(m - 32) * C_ + c];
            else              w = Wv[(m - 64) * C_ + c];
            Ws[cc * WSTR + m] = w;
        }
        __syncthreads();

#pragma unroll 4
        for (int cc = 0; cc < CCH; cc++) {
            float xv = xs[cc * 64 + p];
            unsigned long long xx = pack2(xv, xv);
            const ulonglong2* wr = (const ulonglong2*)(Ws + cc * WSTR + g * 80);
#pragma unroll
            for (int k = 0; k < 20; k++) {
                ulonglong2 w4 = wr[k];
                A[2 * k]     = fma2(xx, w4.x, A[2 * k]);
                A[2 * k + 1] = fma2(xx, w4.y, A[2 * k + 1]);
            }
        }
    }

    const int n = n0 + p;
#pragma unroll
    for (int k = 0; k < 40; k++) {
        float v0, v1;
        unpack2(A[k], v0, v1);
        int o = g * 80 + 2 * k;
        float vals[2] = {v0, v1};
#pragma unroll
        for (int u = 0; u < 2; u++) {
            int oo = o + u;
            float val = vals[u];
            if (oo < 32)
                g_Q[((size_t)b * N_ + n) * DQK + oo] = val + bq[oo];
            else if (oo < 64)
                g_K[((size_t)b * N_ + n) * DQK + (oo - 32)] = val + bk[oo - 32];
            else
                g_V[((size_t)b * N_ + n) * DV + (oo - 64)] = val + bv[oo - 64];
        }
    }
}

// ======================= flash attention kernel (register-tiled) =======================
// CTA: (batch, 64-query-row tile). 256 threads:
//   rowg = t>>4 (16 groups of 4 rows), lane16 = t&15.
// Phase A: thread computes S[4 rows][4 keys], keys j = kk*16 + lane16.
//          softmax state (m,l) kept in registers per row (redundant across 16 lanes).
// Phase B: thread accumulates O[4 rows][16 cols], cols = lane16*16..+15.
//          P broadcast within 16-lane group via shfl (no smem round trip).
constexpr int BM = 64, BN = 64;
constexpr uint32_t AV0 = 0;                 // 64KB
constexpr uint32_t AV1 = 65536;             // 64KB
constexpr uint32_t AK0 = 131072;            // 8KB
constexpr uint32_t AK1 = 131072 + 8192;     // 8KB
constexpr uint32_t AQ  = 147456;            // 8KB
constexpr int ATTN_SMEM = 147456 + 8192;    // 155648

DEVINL uint32_t swz(uint32_t off) { return off ^ ((off >> 3) & 0x70u); }

DEVINL void cp16(uint32_t dst, const void* src) {
    asm volatile("cp.async.cg.shared.global [%0], [%1], 16;" :: "r"(dst), "l"(src));
}

__global__ void __launch_bounds__(256, 1) attn_kernel(float* __restrict__ out)
{
    extern __shared__ __align__(16) char dynsm[];
    const uint32_t sb = (uint32_t)__cvta_generic_to_shared(dynsm);
    const int t    = threadIdx.x;
    const int b    = blockIdx.y;
    const int n0   = blockIdx.x * BM;
    const int rowg = t >> 4;
    const int l16  = t & 15;

    const char* qbase = (const char*)(g_Q + ((size_t)b * N_ + n0) * DQK);
    const char* kbase = (const char*)(g_K + (size_t)b * N_ * DQK);
    const char* vbase = (const char*)(g_V + (size_t)b * N_ * DV);

    // ---- prologue: Q tile (8KB, plain) + K/V tile 0 (swizzled) ----
#pragma unroll
    for (int k = 0; k < 2; k++) {
        uint32_t off = (uint32_t)(t + k * 256) * 16;
        cp16(sb + AQ + off, qbase + off);
    }
#pragma unroll
    for (int k = 0; k < 2; k++) {
        uint32_t off = (uint32_t)(t + k * 256) * 16;
        cp16(sb + AK0 + swz(off), kbase + off);
    }
#pragma unroll
    for (int k = 0; k < 16; k++) {
        uint32_t off = (uint32_t)(t + k * 256) * 16;
        cp16(sb + AV0 + swz(off), vbase + off);
    }
    asm volatile("cp.async.commit_group;");

    // per-row softmax state (4 rows, replicated across the 16-lane group)
    float m_[4], l_[4];
#pragma unroll
    for (int rr = 0; rr < 4; rr++) { m_[rr] = -1e30f; l_[rr] = 0.f; }

    unsigned long long O2[4][8];
#pragma unroll
    for (int rr = 0; rr < 4; rr++)
#pragma unroll
        for (int i = 0; i < 8; i++) O2[rr][i] = 0ull;

    // loop-invariant swizzled offsets
    const int xork = l16 & 7;                     // K: col perm i -> i^xork
    uint32_t soff[4];
#pragma unroll
    for (int sub = 0; sub < 4; sub++)
        soff[sub] = swz((uint32_t)(l16 * 64 + sub * 16));   // V within-row offsets

    const float L2E = 1.4426950408889634f;
    const int NBLK = N_ / BN;   // 64

    for (int blk = 0; blk < NBLK; blk++) {
        const int bi = blk & 1;
        if (blk + 1 < NBLK) {
            const int nb = (blk + 1) & 1;
            const char* kt = kbase + (size_t)(blk + 1) * BN * DQK * 4;
            const char* vt = vbase + (size_t)(blk + 1) * BN * DV * 4;
            const uint32_t kdst = sb + (nb ? AK1 : AK0);
            const uint32_t vdst = sb + (nb ? AV1 : AV0);
#pragma unroll
            for (int k = 0; k < 2; k++) {
                uint32_t off = (uint32_t)(t + k * 256) * 16;
                cp16(kdst + swz(off), kt + off);
            }
#pragma unroll
            for (int k = 0; k < 16; k++) {
                uint32_t off = (uint32_t)(t + k * 256) * 16;
                cp16(vdst + swz(off), vt + off);
            }
            asm volatile("cp.async.commit_group;");
            asm volatile("cp.async.wait_group 1;");
        } else {
            asm volatile("cp.async.wait_group 0;");
        }
        __syncthreads();

        const char* ks = dynsm + (bi ? AK1 : AK0);
        const char* vs = dynsm + (bi ? AV1 : AV0);
        const char* qs = dynsm + AQ;

        // ---- phase A: S[rr][kk], key j = kk*16 + l16 ----
        float p_[4][4];
#pragma unroll
        for (int rr = 0; rr < 4; rr++) {
            // load q row into regs (broadcast across 16 lanes)
            unsigned long long q2[16];
            const ulonglong2* qr = (const ulonglong2*)(qs + (rowg * 4 + rr) * 128);
#pragma unroll
            for (int i = 0; i < 8; i++) {
                ulonglong2 u = qr[i];
                q2[2 * i] = u.x; q2[2 * i + 1] = u.y;
            }
#pragma unroll
            for (int kk = 0; kk < 4; kk++) {
                const char* kr = ks + (kk * 16 + l16) * 128;
                unsigned long long s0 = 0ull, s1 = 0ull;
#pragma unroll
                for (int i = 0; i < 8; i++) {
                    ulonglong2 kv = *(const ulonglong2*)(kr + ((i ^ xork) * 16));
                    s0 = fma2(q2[2 * i], kv.x, s0);
                    s1 = fma2(q2[2 * i + 1], kv.y, s1);
                }
                float a0, a1, c0, c1;
                unpack2(s0, a0, a1);
                unpack2(s1, c0, c1);
                p_[rr][kk] = (a0 + a1) + (c0 + c1);
            }
        }

        // ---- online softmax (per row, within 16-lane group) ----
#pragma unroll
        for (int rr = 0; rr < 4; rr++) {
            float bmax = fmaxf(fmaxf(p_[rr][0], p_[rr][1]), fmaxf(p_[rr][2], p_[rr][3]));
            bmax = fmaxf(bmax, __shfl_xor_sync(0xffffffffu, bmax, 1, 16));
            bmax = fmaxf(bmax, __shfl_xor_sync(0xffffffffu, bmax, 2, 16));
            bmax = fmaxf(bmax, __shfl_xor_sync(0xffffffffu, bmax, 4, 16));
            bmax = fmaxf(bmax, __shfl_xor_sync(0xffffffffu, bmax, 8, 16));
            float mn   = fmaxf(m_[rr], bmax);
            float corr = exp2f((m_[rr] - mn) * L2E);
            float ls = 0.f;
#pragma unroll
            for (int kk = 0; kk < 4; kk++) {
                float pv = exp2f((p_[rr][kk] - mn) * L2E);
                p_[rr][kk] = pv;
                ls += pv;
            }
            ls += __shfl_xor_sync(0xffffffffu, ls, 1, 16);
            ls += __shfl_xor_sync(0xffffffffu, ls, 2, 16);
            ls += __shfl_xor_sync(0xffffffffu, ls, 4, 16);
            ls += __shfl_xor_sync(0xffffffffu, ls, 8, 16);
            l_[rr] = l_[rr] * corr + ls;
            m_[rr] = mn;
            unsigned long long cc2 = pack2(corr, corr);
#pragma unroll
            for (int i = 0; i < 8; i++) O2[rr][i] = mul2(O2[rr][i], cc2);
        }

        // ---- phase B: O[4][16] += P * V ----
#pragma unroll
        for (int kk = 0; kk < 4; kk++) {
#pragma unroll 4
            for (int jg = 0; jg < 16; jg++) {
                // key j = kk*16 + jg; p for row rr lives in lane jg's p_[rr][kk]
                float pj0 = __shfl_sync(0xffffffffu, p_[0][kk], jg, 16);
                float pj1 = __shfl_sync(0xffffffffu, p_[1][kk], jg, 16);
                float pj2 = __shfl_sync(0xffffffffu, p_[2][kk], jg, 16);
                float pj3 = __shfl_sync(0xffffffffu, p_[3][kk], jg, 16);
                const char* vrow = vs + (kk * 16 + jg) * 1024;
                unsigned long long vv[8];
#pragma unroll
                for (int sub = 0; sub < 4; sub++) {
                    ulonglong2 u = *(const ulonglong2*)(vrow + soff[sub]);
                    vv[2 * sub] = u.x; vv[2 * sub + 1] = u.y;
                }
                unsigned long long pp0 = pack2(pj0, pj0);
                unsigned long long pp1 = pack2(pj1, pj1);
                unsigned long long pp2 = pack2(pj2, pj2);
                unsigned long long pp3 = pack2(pj3, pj3);
#pragma unroll
                for (int i = 0; i < 8; i++) {
                    O2[0][i] = fma2(pp0, vv[i], O2[0][i]);
                    O2[1][i] = fma2(pp1, vv[i], O2[1][i]);
                    O2[2][i] = fma2(pp2, vv[i], O2[2][i]);
                    O2[3][i] = fma2(pp3, vv[i], O2[3][i]);
                }
            }
        }
        __syncthreads();
    }

    // ---- epilogue: out[b][c][n] = O / l ----
    float* ob = out + (size_t)b * C_ * N_;
#pragma unroll
    for (int rr = 0; rr < 4; rr++) {
        const float inv = 1.f / l_[rr];
        const int n = n0 + rowg * 4 + rr;
#pragma unroll
        for (int i = 0; i < 8; i++) {
            float v0, v1;
            unpack2(O2[rr][i], v0, v1);
            int c = l16 * 16 + 2 * i;
            ob[(size_t)c * N_ + n]       = v0 * inv;
            ob[(size_t)(c + 1) * N_ + n] = v1 * inv;
        }
    }
}

// ======================= launch =======================
extern "C" void kernel_launch(void* const* d_in, const int* in_sizes, int n_in,
                              void* d_out, int out_size)
{
    const float* x  = (const float*)d_in[0];
    const float* Wq = (const float*)d_in[1];
    const float* bq = (const float*)d_in[2];
    const float* Wk = (const float*)d_in[3];
    const float* bk = (const float*)d_in[4];
    const float* Wv = (const float*)d_in[5];
    const float* bv = (const float*)d_in[6];
    float* out = (float*)d_out;

    cudaFuncSetAttribute(proj_kernel, cudaFuncAttributeMaxDynamicSharedMemorySize, PROJ_SMEM);
    cudaFuncSetAttribute(attn_kernel, cudaFuncAttributeMaxDynamicSharedMemorySize, ATTN_SMEM);

    proj_kernel<<<dim3(N_ / PT, B_), 256, PROJ_SMEM>>>(x, Wq, bq, Wk, bk, Wv, bv);
    attn_kernel<<<dim3(N_ / BM, B_), 256, ATTN_SMEM>>>(out);
}

// round 4
// speedup vs baseline: 2.3937x; 1.0575x over previous
#include <cuda_runtime.h>
#include <cstdint>
#include <cstddef>

#define DEVINL __device__ __forceinline__

// ======================= f32x2 packed helpers (Blackwell FFMA2) =======================
DEVINL unsigned long long pack2(float lo, float hi) {
    unsigned long long d;
    asm("mov.b64 %0, {%1, %2};" : "=l"(d)
        : "r"(__float_as_uint(lo)), "r"(__float_as_uint(hi)));
    return d;
}
DEVINL void unpack2(unsigned long long v, float& lo, float& hi) {
    unsigned int a, b;
    asm("mov.b64 {%0, %1}, %2;" : "=r"(a), "=r"(b) : "l"(v));
    lo = __uint_as_float(a);
    hi = __uint_as_float(b);
}
DEVINL unsigned long long fma2(unsigned long long a, unsigned long long b, unsigned long long c) {
    unsigned long long d;
    asm("fma.rn.f32x2 %0, %1, %2, %3;" : "=l"(d) : "l"(a), "l"(b), "l"(c));
    return d;
}
DEVINL unsigned long long mul2(unsigned long long a, unsigned long long b) {
    unsigned long long d;
    asm("mul.rn.f32x2 %0, %1, %2;" : "=l"(d) : "l"(a), "l"(b));
    return d;
}

// ======================= problem constants =======================
constexpr int B_   = 4;
constexpr int C_   = 256;
constexpr int N_   = 4096;   // H*W
constexpr int DQK  = 32;
constexpr int DV   = 256;

// ======================= scratch (no allocs allowed) =======================
__device__ float g_Q[(size_t)B_ * N_ * DQK];   // [B][N][32]
__device__ float g_K[(size_t)B_ * N_ * DQK];   // [B][N][32]
__device__ float g_V[(size_t)B_ * N_ * DV];    // [B][N][256]

// ======================= projection kernel =======================
constexpr int PT     = 64;
constexpr int MTOT   = 320;
constexpr int CCH    = 64;
constexpr int WSTR   = 324;
constexpr int OSTR   = 321;   // padded output staging stride (floats)
constexpr int PROJ_SMEM = (CCH * PT + CCH * WSTR) * 4;   // 99328 >= PT*OSTR*4=82176

__global__ void __launch_bounds__(256, 2) proj_kernel(
    const float* __restrict__ x,
    const float* __restrict__ Wq, const float* __restrict__ bq,
    const float* __restrict__ Wk, const float* __restrict__ bk,
    const float* __restrict__ Wv, const float* __restrict__ bv)
{
    extern __shared__ __align__(16) char dynsm[];
    float* xs = (float*)dynsm;
    float* Ws = (float*)dynsm + CCH * PT;

    const int t  = threadIdx.x;
    const int b  = blockIdx.y;
    const int n0 = blockIdx.x * PT;
    const int p  = t & 63;
    const int g  = t >> 6;

    unsigned long long A[40];
#pragma unroll
    for (int k = 0; k < 40; k++) A[k] = 0ull;

    for (int c0 = 0; c0 < C_; c0 += CCH) {
        __syncthreads();
#pragma unroll
        for (int k = 0; k < (CCH * PT) / 256; k++) {
            int idx = t + k * 256;
            int cc = idx >> 6, pp = idx & 63;
            xs[idx] = x[((size_t)b * C_ + (c0 + cc)) * N_ + (n0 + pp)];
        }
        for (int idx = t; idx < MTOT * CCH; idx += 256) {
            int m = idx / CCH, cc = idx % CCH;
            int c = c0 + cc;
            float w;
            if (m < 32)       w = Wq[m * C_ + c];
            else if (m < 64)  w = Wk[(m - 32) * C_ + c];
            else              w = Wv[(m - 64) * C_ + c];
            Ws[cc * WSTR + m] = w;
        }
        __syncthreads();

#pragma unroll 4
        for (int cc = 0; cc < CCH; cc++) {
            float xv = xs[cc * 64 + p];
            unsigned long long xx = pack2(xv, xv);
            const ulonglong2* wr = (const ulonglong2*)(Ws + cc * WSTR + g * 80);
#pragma unroll
            for (int k = 0; k < 20; k++) {
                ulonglong2 w4 = wr[k];
                A[2 * k]     = fma2(xx, w4.x, A[2 * k]);
                A[2 * k + 1] = fma2(xx, w4.y, A[2 * k + 1]);
            }
        }
    }

    // ---- stage results into smem (bias added), then write coalesced ----
    __syncthreads();
    float* so = (float*)dynsm;   // [PT][OSTR]
#pragma unroll
    for (int k = 0; k < 40; k++) {
        float v0, v1;
        unpack2(A[k], v0, v1);
        int o = g * 80 + 2 * k;
        float bb0, bb1;
        if (o < 32)       { bb0 = bq[o];       bb1 = bq[o + 1]; }
        else if (o < 64)  { bb0 = bk[o - 32];  bb1 = bk[o - 31]; }
        else              { bb0 = bv[o - 64];  bb1 = bv[o - 63]; }
        so[p * OSTR + o]     = v0 + bb0;
        so[p * OSTR + o + 1] = v1 + bb1;
    }
    __syncthreads();

    // coalesced global writes: consecutive threads -> consecutive m
#pragma unroll
    for (int k = 0; k < (PT * MTOT) / 256; k++) {
        int idx = t + k * 256;
        int pp = idx / MTOT, m = idx % MTOT;
        float val = so[pp * OSTR + m];
        int n = n0 + pp;
        if (m < 32)
            g_Q[((size_t)b * N_ + n) * DQK + m] = val;
        else if (m < 64)
            g_K[((size_t)b * N_ + n) * DQK + (m - 32)] = val;
        else
            g_V[((size_t)b * N_ + n) * DV + (m - 64)] = val;
    }
}

// ======================= flash attention kernel =======================
// CTA: (batch, 64-query-row tile). 256 threads = 8 warps.
// warp w owns rows w*8..w*8+7; lane owns cols lane*8..lane*8+7 (phase B)
// and keys j = kk*32 + lane (phase A).
constexpr int BM = 64, BN = 64;
constexpr uint32_t AV0 = 0;                 // 64KB
constexpr uint32_t AV1 = 65536;             // 64KB
constexpr uint32_t AK0 = 131072;            // 8KB
constexpr uint32_t AK1 = 131072 + 8192;     // 8KB
constexpr uint32_t AQ  = 147456;            // 8KB
constexpr int ATTN_SMEM = 147456 + 8192;    // 155648

DEVINL uint32_t swz(uint32_t off) { return off ^ ((off >> 3) & 0x70u); }

DEVINL void cp16(uint32_t dst, const void* src) {
    asm volatile("cp.async.cg.shared.global [%0], [%1], 16;" :: "r"(dst), "l"(src));
}

__global__ void __launch_bounds__(256, 1) attn_kernel(float* __restrict__ out)
{
    extern __shared__ __align__(16) char dynsm[];
    const uint32_t sb = (uint32_t)__cvta_generic_to_shared(dynsm);
    const int t    = threadIdx.x;
    const int b    = blockIdx.y;
    const int n0   = blockIdx.x * BM;
    const int w    = t >> 5;     // warp: rows w*8..w*8+7
    const int lane = t & 31;     // cols lane*8..+7 / keys kk*32+lane

    const char* qbase = (const char*)(g_Q + ((size_t)b * N_ + n0) * DQK);
    const char* kbase = (const char*)(g_K + (size_t)b * N_ * DQK);
    const char* vbase = (const char*)(g_V + (size_t)b * N_ * DV);

    // ---- prologue: Q tile (8KB, plain) + K/V tile 0 (swizzled) ----
#pragma unroll
    for (int k = 0; k < 2; k++) {
        uint32_t off = (uint32_t)(t + k * 256) * 16;
        cp16(sb + AQ + off, qbase + off);
    }
#pragma unroll
    for (int k = 0; k < 2; k++) {
        uint32_t off = (uint32_t)(t + k * 256) * 16;
        cp16(sb + AK0 + swz(off), kbase + off);
    }
#pragma unroll
    for (int k = 0; k < 16; k++) {
        uint32_t off = (uint32_t)(t + k * 256) * 16;
        cp16(sb + AV0 + swz(off), vbase + off);
    }
    asm volatile("cp.async.commit_group;");

    // softmax state: 8 rows (replicated across the 32 lanes of the warp)
    float m_[8], l_[8];
#pragma unroll
    for (int rr = 0; rr < 8; rr++) { m_[rr] = -1e30f; l_[rr] = 0.f; }

    // O accumulators: 8 rows x 8 cols (4 f32x2 per row)
    unsigned long long O2[8][4];
#pragma unroll
    for (int rr = 0; rr < 8; rr++)
#pragma unroll
        for (int i = 0; i < 4; i++) O2[rr][i] = 0ull;

    // loop-invariant swizzled offsets
    const int xork = lane & 7;                 // K row read perm
    const uint32_t voff0 = swz((uint32_t)(lane * 32));
    const uint32_t voff1 = swz((uint32_t)(lane * 32 + 16));

    const float L2E = 1.4426950408889634f;
    const int NBLK = N_ / BN;   // 64

    for (int blk = 0; blk < NBLK; blk++) {
        const int bi = blk & 1;
        if (blk + 1 < NBLK) {
            const int nb = (blk + 1) & 1;
            const char* kt = kbase + (size_t)(blk + 1) * BN * DQK * 4;
            const char* vt = vbase + (size_t)(blk + 1) * BN * DV * 4;
            const uint32_t kdst = sb + (nb ? AK1 : AK0);
            const uint32_t vdst = sb + (nb ? AV1 : AV0);
#pragma unroll
            for (int k = 0; k < 2; k++) {
                uint32_t off = (uint32_t)(t + k * 256) * 16;
                cp16(kdst + swz(off), kt + off);
            }
#pragma unroll
            for (int k = 0; k < 16; k++) {
                uint32_t off = (uint32_t)(t + k * 256) * 16;
                cp16(vdst + swz(off), vt + off);
            }
            asm volatile("cp.async.commit_group;");
            asm volatile("cp.async.wait_group 1;");
        } else {
            asm volatile("cp.async.wait_group 0;");
        }
        __syncthreads();

        const char* ks = dynsm + (bi ? AK1 : AK0);
        const char* vs = dynsm + (bi ? AV1 : AV0);
        const char* qs = dynsm + AQ;

        // ---- phase A: S[rr][kk], key j = kk*32 + lane ----
        float p_[8][2];
#pragma unroll
        for (int kk = 0; kk < 2; kk++) {
            // hoist this lane's K row into registers (16 f32x2)
            unsigned long long k2[16];
            const char* kr = ks + (kk * 32 + lane) * 128;
#pragma unroll
            for (int i = 0; i < 8; i++) {
                ulonglong2 kv = *(const ulonglong2*)(kr + ((i ^ xork) * 16));
                k2[2 * i] = kv.x; k2[2 * i + 1] = kv.y;
            }
#pragma unroll
            for (int rr = 0; rr < 8; rr++) {
                const ulonglong2* qr = (const ulonglong2*)(qs + (w * 8 + rr) * 128);
                unsigned long long s0 = 0ull, s1 = 0ull;
#pragma unroll
                for (int i = 0; i < 8; i++) {
                    ulonglong2 qv = qr[i];            // broadcast LDS
                    s0 = fma2(qv.x, k2[2 * i], s0);
                    s1 = fma2(qv.y, k2[2 * i + 1], s1);
                }
                float a0, a1, c0, c1;
                unpack2(s0, a0, a1);
                unpack2(s1, c0, c1);
                p_[rr][kk] = (a0 + a1) + (c0 + c1);
            }
        }

        // ---- online softmax (per row, across full warp) ----
        float corr_[8];
#pragma unroll
        for (int rr = 0; rr < 8; rr++) {
            float bmax = fmaxf(p_[rr][0], p_[rr][1]);
#pragma unroll
            for (int d = 16; d >= 1; d >>= 1)
                bmax = fmaxf(bmax, __shfl_xor_sync(0xffffffffu, bmax, d, 32));
            float mn   = fmaxf(m_[rr], bmax);
            float corr = exp2f((m_[rr] - mn) * L2E);
            float p0 = exp2f((p_[rr][0] - mn) * L2E);
            float p1 = exp2f((p_[rr][1] - mn) * L2E);
            p_[rr][0] = p0; p_[rr][1] = p1;
            float ls = p0 + p1;
#pragma unroll
            for (int d = 16; d >= 1; d >>= 1)
                ls += __shfl_xor_sync(0xffffffffu, ls, d, 32);
            l_[rr] = l_[rr] * corr + ls;
            m_[rr] = mn;
            corr_[rr] = corr;
        }
#pragma unroll
        for (int rr = 0; rr < 8; rr++) {
            unsigned long long cc2 = pack2(corr_[rr], corr_[rr]);
#pragma unroll
            for (int i = 0; i < 4; i++) O2[rr][i] = mul2(O2[rr][i], cc2);
        }

        // ---- phase B: O[8][8] += P * V ----
#pragma unroll
        for (int kk = 0; kk < 2; kk++) {
#pragma unroll 4
            for (int jg = 0; jg < 32; jg++) {
                const char* vrow = vs + (kk * 32 + jg) * 1024;
                ulonglong2 u0 = *(const ulonglong2*)(vrow + voff0);
                ulonglong2 u1 = *(const ulonglong2*)(vrow + voff1);
                unsigned long long pp[8];
#pragma unroll
                for (int rr = 0; rr < 8; rr++) {
                    float pj = __shfl_sync(0xffffffffu, p_[rr][kk], jg, 32);
                    pp[rr] = pack2(pj, pj);
                }
#pragma unroll
                for (int rr = 0; rr < 8; rr++) {
                    O2[rr][0] = fma2(pp[rr], u0.x, O2[rr][0]);
                    O2[rr][1] = fma2(pp[rr], u0.y, O2[rr][1]);
                    O2[rr][2] = fma2(pp[rr], u1.x, O2[rr][2]);
                    O2[rr][3] = fma2(pp[rr], u1.y, O2[rr][3]);
                }
            }
        }
        __syncthreads();
    }

    // ---- epilogue: out[b][c][n] = O / l ----
    float* ob = out + (size_t)b * C_ * N_;
#pragma unroll
    for (int rr = 0; rr < 8; rr++) {
        const float inv = 1.f / l_[rr];
        const int n = n0 + w * 8 + rr;
#pragma unroll
        for (int i = 0; i < 4; i++) {
            float v0, v1;
            unpack2(O2[rr][i], v0, v1);
            int c = lane * 8 + 2 * i;
            ob[(size_t)c * N_ + n]       = v0 * inv;
            ob[(size_t)(c + 1) * N_ + n] = v1 * inv;
        }
    }
}

// ======================= launch =======================
extern "C" void kernel_launch(void* const* d_in, const int* in_sizes, int n_in,
                              void* d_out, int out_size)
{
    const float* x  = (const float*)d_in[0];
    const float* Wq = (const float*)d_in[1];
    const float* bq = (const float*)d_in[2];
    const float* Wk = (const float*)d_in[3];
    const float* bk = (const float*)d_in[4];
    const float* Wv = (const float*)d_in[5];
    const float* bv = (const float*)d_in[6];
    float* out = (float*)d_out;

    cudaFuncSetAttribute(proj_kernel, cudaFuncAttributeMaxDynamicSharedMemorySize, PROJ_SMEM);
    cudaFuncSetAttribute(attn_kernel, cudaFuncAttributeMaxDynamicSharedMemorySize, ATTN_SMEM);

    proj_kernel<<<dim3(N_ / PT, B_), 256, PROJ_SMEM>>>(x, Wq, bq, Wk, bk, Wv, bv);
    attn_kernel<<<dim3(N_ / BM, B_), 256, ATTN_SMEM>>>(out);
}